// round 1
// baseline (speedup 1.0000x reference)
#include <cuda_runtime.h>
#include <math.h>

#define DD 128          // feature dim D = H1
#define NB 4            // nodes per block
#define NROWS (NB * 6)  // 24 layer-1 rows per block (1 self + 5 children per node)

__device__ __forceinline__ float sigmoidf_(float v) {
    return 1.0f / (1.0f + expf(-v));
}

__device__ __forceinline__ void fma4(float& acc, float4 w, float4 v) {
    acc = fmaf(w.x, v.x, acc);
    acc = fmaf(w.y, v.y, acc);
    acc = fmaf(w.z, v.z, acc);
    acc = fmaf(w.w, v.w, acc);
}

__global__ void __launch_bounds__(128, 4)
signn_fused(const float* __restrict__ h0, const float* __restrict__ h1,
            const float* __restrict__ h2,
            const float* __restrict__ Wl1, const float* __restrict__ Wr1,
            const float* __restrict__ Wlt1, const float* __restrict__ Wrt1,
            const float* __restrict__ Wl2, const float* __restrict__ Wr2,
            const float* __restrict__ Wlt2, const float* __restrict__ Wrt2,
            float* __restrict__ out, int N)
{
    __shared__ float xs[NROWS][DD];   // x_self rows
    __shared__ float ns[NROWS][DD];   // neigh rows
    __shared__ float l2x[NB][DD];     // h0p
    __shared__ float l2n[NB][DD];     // neigh2

    const int tid = threadIdx.x;
    const int i0  = blockIdx.x * NB;

    // ---- load x_self rows: xs[6m] = h0[i0+m]; xs[6m+1+s] = h1[(i0+m)*5 + s] ----
    {
        int r = tid >> 5;   // node 0..3
        int c = tid & 31;   // float4 column
        int node = min(i0 + r, N - 1);
        float4 v = ((const float4*)h0)[(size_t)node * 32 + c];
        *((float4*)&xs[r * 6][c * 4]) = v;
    }
#pragma unroll
    for (int q = 0; q < 5; q++) {
        int idx = q * 128 + tid;   // 0..639 covers 20 rows x 32 float4
        int row = idx >> 5;        // 0..19 = m*5 + s
        int c   = idx & 31;
        int m = row / 5, s = row - m * 5;
        long grow = (long)min(i0 + m, N - 1) * 5 + s;
        float4 v = ((const float4*)h1)[grow * 32 + c];
        *((float4*)&xs[m * 6 + 1 + s][c * 4]) = v;
    }
    // ---- neigh rows for h1-children: pairwise mean of two h2 rows ----
#pragma unroll
    for (int q = 0; q < 5; q++) {
        int idx = q * 128 + tid;
        int row = idx >> 5;        // 0..19
        int c   = idx & 31;
        int m = row / 5, s = row - m * 5;
        long g = ((long)min(i0 + m, N - 1) * 5 + s) * 2;
        float4 a = ((const float4*)h2)[g * 32 + c];
        float4 b = ((const float4*)h2)[(g + 1) * 32 + c];
        float4 o;
        o.x = 0.5f * (a.x + b.x);
        o.y = 0.5f * (a.y + b.y);
        o.z = 0.5f * (a.z + b.z);
        o.w = 0.5f * (a.w + b.w);
        *((float4*)&ns[m * 6 + 1 + s][c * 4]) = o;
    }
    __syncthreads();

    // ---- neigh row for self node: mean of its 5 h1 rows (already in xs) ----
#pragma unroll
    for (int q = 0; q < 4; q++) {
        int idx = q * 128 + tid;   // 0..511 covers 4 rows x 128
        int m = idx >> 7;
        int k = idx & 127;
        float a = xs[m * 6 + 1][k] + xs[m * 6 + 2][k];
        a += xs[m * 6 + 3][k];
        a += xs[m * 6 + 4][k];
        a += xs[m * 6 + 5][k];
        ns[m * 6][k] = a * 0.2f;
    }
    __syncthreads();

    // ---- layer-1 GEMV: thread j = tid owns output feature j for all 24 rows ----
    float accx[NROWS], acct[NROWS];
#pragma unroll
    for (int r = 0; r < NROWS; r++) { accx[r] = 0.0f; acct[r] = 0.0f; }
    {
        const float4* wl  = (const float4*)(Wl1  + tid * DD);
        const float4* wr  = (const float4*)(Wr1  + tid * DD);
        const float4* wlt = (const float4*)(Wlt1 + tid * DD);
        const float4* wrt = (const float4*)(Wrt1 + tid * DD);
#pragma unroll 1
        for (int k4 = 0; k4 < 32; k4++) {
            float4 a = wl[k4], b = wr[k4], c = wlt[k4], d = wrt[k4];
#pragma unroll
            for (int r = 0; r < NROWS; r++) {
                float4 xv = *((const float4*)&xs[r][k4 * 4]);
                float4 nv = *((const float4*)&ns[r][k4 * 4]);
                fma4(accx[r], a, xv);
                fma4(accx[r], b, nv);
                fma4(acct[r], c, xv);
                fma4(acct[r], d, nv);
            }
        }
    }

    // ---- layer-1 epilogue: out_s = sigmoid(accx) * (acct >= 1) ; build h0p / neigh2 ----
#pragma unroll
    for (int m = 0; m < NB; m++) {
        float s0 = sigmoidf_(accx[m * 6]) * (acct[m * 6] >= 1.0f ? 1.0f : 0.0f);
        l2x[m][tid] = s0;
        float v1 = sigmoidf_(accx[m * 6 + 1]) * (acct[m * 6 + 1] >= 1.0f ? 1.0f : 0.0f);
        float v2 = sigmoidf_(accx[m * 6 + 2]) * (acct[m * 6 + 2] >= 1.0f ? 1.0f : 0.0f);
        float v3 = sigmoidf_(accx[m * 6 + 3]) * (acct[m * 6 + 3] >= 1.0f ? 1.0f : 0.0f);
        float v4 = sigmoidf_(accx[m * 6 + 4]) * (acct[m * 6 + 4] >= 1.0f ? 1.0f : 0.0f);
        float v5 = sigmoidf_(accx[m * 6 + 5]) * (acct[m * 6 + 5] >= 1.0f ? 1.0f : 0.0f);
        float sum = v1 + v2;
        sum += v3; sum += v4; sum += v5;
        l2n[m][tid] = sum * 0.2f;
    }
    __syncthreads();

    // ---- layer-2: 4 nodes x 64 outputs = 256 outputs; each thread does 2 ----
    {
        int jj    = tid & 63;
        int mbase = tid >> 6;   // 0 or 1; thread handles nodes mbase and mbase+2
        const float4* wl  = (const float4*)(Wl2  + jj * DD);
        const float4* wr  = (const float4*)(Wr2  + jj * DD);
        const float4* wlt = (const float4*)(Wlt2 + jj * DD);
        const float4* wrt = (const float4*)(Wrt2 + jj * DD);
        float ax[2] = {0.0f, 0.0f}, at[2] = {0.0f, 0.0f};
#pragma unroll 1
        for (int k4 = 0; k4 < 32; k4++) {
            float4 a = wl[k4], b = wr[k4], c = wlt[k4], d = wrt[k4];
#pragma unroll
            for (int u = 0; u < 2; u++) {
                int m = mbase + u * 2;
                float4 xv = *((const float4*)&l2x[m][k4 * 4]);
                float4 nv = *((const float4*)&l2n[m][k4 * 4]);
                fma4(ax[u], a, xv);
                fma4(ax[u], b, nv);
                fma4(at[u], c, xv);
                fma4(at[u], d, nv);
            }
        }
#pragma unroll
        for (int u = 0; u < 2; u++) {
            int node = i0 + mbase + u * 2;
            if (node < N) {
                out[(size_t)node * 64 + jj] =
                    sigmoidf_(ax[u]) * (at[u] >= 1.0f ? 1.0f : 0.0f);
            }
        }
    }
}

extern "C" void kernel_launch(void* const* d_in, const int* in_sizes, int n_in,
                              void* d_out, int out_size)
{
    const float* h0   = (const float*)d_in[0];
    const float* h1   = (const float*)d_in[1];
    const float* h2   = (const float*)d_in[2];
    const float* Wl1  = (const float*)d_in[3];
    const float* Wr1  = (const float*)d_in[4];
    const float* Wlt1 = (const float*)d_in[5];
    const float* Wrt1 = (const float*)d_in[6];
    const float* Wl2  = (const float*)d_in[7];
    const float* Wr2  = (const float*)d_in[8];
    const float* Wlt2 = (const float*)d_in[9];
    const float* Wrt2 = (const float*)d_in[10];

    int N = in_sizes[0] / DD;
    int grid = (N + NB - 1) / NB;
    signn_fused<<<grid, 128>>>(h0, h1, h2,
                               Wl1, Wr1, Wlt1, Wrt1,
                               Wl2, Wr2, Wlt2, Wrt2,
                               (float*)d_out, N);
}

// round 2
// speedup vs baseline: 1.7890x; 1.7890x over previous
#include <cuda_runtime.h>
#include <math.h>
#include <stdint.h>

// Layer-1 out_s scratch: 600000 rows x 128 feats
__device__ float g_outs[76800000];

__device__ __forceinline__ void split_tf32(float x, uint32_t &hi, uint32_t &lo) {
    uint32_t h, l;
    asm("cvt.rna.tf32.f32 %0, %1;" : "=r"(h) : "f"(x));
    float r = x - __uint_as_float(h);
    asm("cvt.rna.tf32.f32 %0, %1;" : "=r"(l) : "f"(r));
    hi = h; lo = l;
}

__device__ __forceinline__ void mma8(float c[4], const uint32_t a[4], uint32_t b0, uint32_t b1) {
    asm volatile(
        "mma.sync.aligned.m16n8k8.row.col.f32.tf32.tf32.f32 "
        "{%0,%1,%2,%3}, {%4,%5,%6,%7}, {%8,%9}, {%0,%1,%2,%3};"
        : "+f"(c[0]), "+f"(c[1]), "+f"(c[2]), "+f"(c[3])
        : "r"(a[0]), "r"(a[1]), "r"(a[2]), "r"(a[3]), "r"(b0), "r"(b1));
}

__device__ __forceinline__ float sigmoidf_(float v) {
    return 1.0f / (1.0f + expf(-v));
}

// ---------------------------------------------------------------------------
// Kernel 1: layer-1.  Virtual GEMM rows r in [0, 6N):
//   r <  N : x_self = h0[r],        neigh = mean_{s<5} h1[5r+s]
//   r >= N : x_self = h1[r-N],      neigh = mean(h2[2(r-N)], h2[2(r-N)+1])
// A[r] = [x_self(128) | neigh(128)]  (K = 256)
// B interleaved: col 2j -> [Wl1;Wr1] row j, col 2j+1 -> [Wlt1;Wrt1] row j (N = 256)
// out_s[r][j] = sigmoid(D[r][2j]) * (D[r][2j+1] >= 1)
// Tile: BM=128, BN=256(all), BK=32 chunks; 512 thr = 16 warps (4M x 4N),
// warp tile 32x64 = 2 m-tiles x 8 n-tiles.
// ---------------------------------------------------------------------------
#define AS 260
#define BS 36

__global__ void __launch_bounds__(512, 1)
signn_l1(const float* __restrict__ h0, const float* __restrict__ h1,
         const float* __restrict__ h2,
         const float* __restrict__ Wl1, const float* __restrict__ Wr1,
         const float* __restrict__ Wlt1, const float* __restrict__ Wrt1,
         int N)
{
    extern __shared__ float sm[];
    float* Asm = sm;                 // [128][260]
    float* BsH = sm + 128 * AS;      // [256][36]
    float* BsL = BsH + 256 * BS;     // [256][36]

    const int tid = threadIdx.x;
    const int w = tid >> 5, l = tid & 31;
    const int g = l >> 2, tig = l & 3;
    const long rows = 6L * N;
    const long blockRow = (long)blockIdx.x * 128;

    // ---- stage A (full K=256) ----
    for (int rr = 0; rr < 8; rr++) {
        int row = w * 8 + rr;
        long gr = blockRow + row;
        long grc = gr < rows ? gr : rows - 1;
        float4 xv, nv;
        if (grc < N) {
            xv = ((const float4*)h0)[grc * 32 + l];
            const float4* p = (const float4*)h1 + grc * 5 * 32 + l;
            float4 a0 = p[0], a1 = p[32], a2 = p[64], a3 = p[96], a4 = p[128];
            nv.x = (a0.x + a1.x + a2.x + a3.x + a4.x) * 0.2f;
            nv.y = (a0.y + a1.y + a2.y + a3.y + a4.y) * 0.2f;
            nv.z = (a0.z + a1.z + a2.z + a3.z + a4.z) * 0.2f;
            nv.w = (a0.w + a1.w + a2.w + a3.w + a4.w) * 0.2f;
        } else {
            long q = grc - N;
            xv = ((const float4*)h1)[q * 32 + l];
            const float4* p = (const float4*)h2 + q * 2 * 32 + l;
            float4 a0 = p[0], a1 = p[32];
            nv.x = (a0.x + a1.x) * 0.5f;
            nv.y = (a0.y + a1.y) * 0.5f;
            nv.z = (a0.z + a1.z) * 0.5f;
            nv.w = (a0.w + a1.w) * 0.5f;
        }
        *(float4*)&Asm[row * AS + 4 * l] = xv;
        *(float4*)&Asm[row * AS + 128 + 4 * l] = nv;
    }

    const int warpM = w >> 2, warpN = w & 3;
    float acc[2][8][4];
#pragma unroll
    for (int mt = 0; mt < 2; mt++)
#pragma unroll
        for (int nti = 0; nti < 8; nti++)
#pragma unroll
            for (int e = 0; e < 4; e++) acc[mt][nti][e] = 0.0f;

    for (int kc = 0; kc < 256; kc += 32) {
        __syncthreads();
        // ---- stage B chunk, pre-split hi/lo ----
#pragma unroll
        for (int it = 0; it < 4; it++) {
            int idx = it * 512 + tid;
            int k4 = idx & 7, col = idx >> 3;       // col 0..255
            int j = col >> 1, tt = col & 1;
            int gk = kc + 4 * k4;
            const float* base = (gk < 128) ? (tt ? Wlt1 : Wl1) : (tt ? Wrt1 : Wr1);
            float4 v = *(const float4*)(base + j * 128 + (gk & 127));
            uint32_t hx, lx, hy, ly, hz, lz, hw, lw;
            split_tf32(v.x, hx, lx); split_tf32(v.y, hy, ly);
            split_tf32(v.z, hz, lz); split_tf32(v.w, hw, lw);
            float4 vh = make_float4(__uint_as_float(hx), __uint_as_float(hy),
                                    __uint_as_float(hz), __uint_as_float(hw));
            float4 vl = make_float4(__uint_as_float(lx), __uint_as_float(ly),
                                    __uint_as_float(lz), __uint_as_float(lw));
            *(float4*)&BsH[col * BS + 4 * k4] = vh;
            *(float4*)&BsL[col * BS + 4 * k4] = vl;
        }
        __syncthreads();

#pragma unroll
        for (int ks = 0; ks < 4; ks++) {
            int kg = kc + ks * 8;   // global k of this 8-step
            int kl = ks * 8;        // local k within B chunk
            uint32_t ah[2][4], al[2][4];
#pragma unroll
            for (int mt = 0; mt < 2; mt++) {
                int r0 = (warpM * 32 + mt * 16 + g) * AS;
                split_tf32(Asm[r0 + kg + tig],              ah[mt][0], al[mt][0]);
                split_tf32(Asm[r0 + 8 * AS + kg + tig],     ah[mt][1], al[mt][1]);
                split_tf32(Asm[r0 + kg + tig + 4],          ah[mt][2], al[mt][2]);
                split_tf32(Asm[r0 + 8 * AS + kg + tig + 4], ah[mt][3], al[mt][3]);
            }
#pragma unroll
            for (int nti = 0; nti < 8; nti++) {
                int nb = (warpN * 64 + nti * 8 + g) * BS + kl + tig;
                uint32_t bh0 = __float_as_uint(BsH[nb]);
                uint32_t bl0 = __float_as_uint(BsL[nb]);
                uint32_t bh1 = __float_as_uint(BsH[nb + 4]);
                uint32_t bl1 = __float_as_uint(BsL[nb + 4]);
#pragma unroll
                for (int mt = 0; mt < 2; mt++) {
                    mma8(acc[mt][nti], ah[mt], bh0, bh1);
                    mma8(acc[mt][nti], ah[mt], bl0, bl1);
                    mma8(acc[mt][nti], al[mt], bh0, bh1);
                }
            }
        }
    }

    // ---- epilogue: out_s = sigmoid(x) * spike(t), guarded near threshold ----
#pragma unroll
    for (int mt = 0; mt < 2; mt++) {
#pragma unroll
        for (int nti = 0; nti < 8; nti++) {
            int j = warpN * 32 + nti * 4 + tig;
#pragma unroll
            for (int half = 0; half < 2; half++) {
                int rloc = warpM * 32 + mt * 16 + g + half * 8;
                long gr = blockRow + rloc;
                if (gr < rows) {
                    float x = acc[mt][nti][half * 2 + 0];
                    float t = acc[mt][nti][half * 2 + 1];
                    if (fabsf(t - 1.0f) < 1e-3f) {
                        float s = 0.0f;
                        const float* ar = &Asm[rloc * AS];
                        const float* wt = Wlt1 + j * 128;
                        const float* wr = Wrt1 + j * 128;
#pragma unroll 4
                        for (int k = 0; k < 128; k++) s += ar[k] * wt[k];
#pragma unroll 4
                        for (int k = 0; k < 128; k++) s += ar[128 + k] * wr[k];
                        t = s;
                    }
                    float sg = sigmoidf_(x);
                    g_outs[gr * 128 + j] = (t >= 1.0f) ? sg : 0.0f;
                }
            }
        }
    }
}

// ---------------------------------------------------------------------------
// Kernel 2: layer-2.  Rows = nodes (N).  A2[n] = [h0p(n) | mean5 h1p(n)] (K=256)
// B2 interleaved: col 2j -> [Wl2;Wr2] row j, col 2j+1 -> [Wlt2;Wrt2] row j (N=128)
// out[n][j] = sigmoid(D[n][2j]) * (D[n][2j+1] >= 1)
// Tile: BM=128 nodes, BN=128(all), BK=32; 256 thr = 8 warps (4M x 2N).
// ---------------------------------------------------------------------------
__global__ void __launch_bounds__(256, 1)
signn_l2(const float* __restrict__ Wl2, const float* __restrict__ Wr2,
         const float* __restrict__ Wlt2, const float* __restrict__ Wrt2,
         float* __restrict__ out, int N)
{
    extern __shared__ float sm[];
    float* Asm = sm;                 // [128][260]
    float* BsH = sm + 128 * AS;      // [128][36]
    float* BsL = BsH + 128 * BS;

    const int tid = threadIdx.x;
    const int w = tid >> 5, l = tid & 31;
    const int g = l >> 2, tig = l & 3;
    const long blockRow = (long)blockIdx.x * 128;

    // ---- stage A2 from layer-1 scratch ----
    for (int rr = 0; rr < 16; rr++) {
        int row = w * 16 + rr;
        long gn = blockRow + row;
        long gnc = gn < N ? gn : N - 1;
        float4 xv = ((const float4*)g_outs)[gnc * 32 + l];
        const float4* p = (const float4*)g_outs + ((long)N + gnc * 5) * 32 + l;
        float4 a0 = p[0], a1 = p[32], a2 = p[64], a3 = p[96], a4 = p[128];
        float4 nv;
        nv.x = (a0.x + a1.x + a2.x + a3.x + a4.x) * 0.2f;
        nv.y = (a0.y + a1.y + a2.y + a3.y + a4.y) * 0.2f;
        nv.z = (a0.z + a1.z + a2.z + a3.z + a4.z) * 0.2f;
        nv.w = (a0.w + a1.w + a2.w + a3.w + a4.w) * 0.2f;
        *(float4*)&Asm[row * AS + 4 * l] = xv;
        *(float4*)&Asm[row * AS + 128 + 4 * l] = nv;
    }

    const int warpM = w >> 1, warpN = w & 1;
    float acc[2][8][4];
#pragma unroll
    for (int mt = 0; mt < 2; mt++)
#pragma unroll
        for (int nti = 0; nti < 8; nti++)
#pragma unroll
            for (int e = 0; e < 4; e++) acc[mt][nti][e] = 0.0f;

    for (int kc = 0; kc < 256; kc += 32) {
        __syncthreads();
#pragma unroll
        for (int it = 0; it < 4; it++) {
            int idx = it * 256 + tid;
            int k4 = idx & 7, col = idx >> 3;       // col 0..127
            int j = col >> 1, tt = col & 1;
            int gk = kc + 4 * k4;
            const float* base = (gk < 128) ? (tt ? Wlt2 : Wl2) : (tt ? Wrt2 : Wr2);
            float4 v = *(const float4*)(base + j * 128 + (gk & 127));
            uint32_t hx, lx, hy, ly, hz, lz, hw, lw;
            split_tf32(v.x, hx, lx); split_tf32(v.y, hy, ly);
            split_tf32(v.z, hz, lz); split_tf32(v.w, hw, lw);
            float4 vh = make_float4(__uint_as_float(hx), __uint_as_float(hy),
                                    __uint_as_float(hz), __uint_as_float(hw));
            float4 vl = make_float4(__uint_as_float(lx), __uint_as_float(ly),
                                    __uint_as_float(lz), __uint_as_float(lw));
            *(float4*)&BsH[col * BS + 4 * k4] = vh;
            *(float4*)&BsL[col * BS + 4 * k4] = vl;
        }
        __syncthreads();

#pragma unroll
        for (int ks = 0; ks < 4; ks++) {
            int kg = kc + ks * 8;
            int kl = ks * 8;
            uint32_t ah[2][4], al[2][4];
#pragma unroll
            for (int mt = 0; mt < 2; mt++) {
                int r0 = (warpM * 32 + mt * 16 + g) * AS;
                split_tf32(Asm[r0 + kg + tig],              ah[mt][0], al[mt][0]);
                split_tf32(Asm[r0 + 8 * AS + kg + tig],     ah[mt][1], al[mt][1]);
                split_tf32(Asm[r0 + kg + tig + 4],          ah[mt][2], al[mt][2]);
                split_tf32(Asm[r0 + 8 * AS + kg + tig + 4], ah[mt][3], al[mt][3]);
            }
#pragma unroll
            for (int nti = 0; nti < 8; nti++) {
                int nb = (warpN * 64 + nti * 8 + g) * BS + kl + tig;
                uint32_t bh0 = __float_as_uint(BsH[nb]);
                uint32_t bl0 = __float_as_uint(BsL[nb]);
                uint32_t bh1 = __float_as_uint(BsH[nb + 4]);
                uint32_t bl1 = __float_as_uint(BsL[nb + 4]);
#pragma unroll
                for (int mt = 0; mt < 2; mt++) {
                    mma8(acc[mt][nti], ah[mt], bh0, bh1);
                    mma8(acc[mt][nti], ah[mt], bl0, bl1);
                    mma8(acc[mt][nti], al[mt], bh0, bh1);
                }
            }
        }
    }

#pragma unroll
    for (int mt = 0; mt < 2; mt++) {
#pragma unroll
        for (int nti = 0; nti < 8; nti++) {
            int j = warpN * 32 + nti * 4 + tig;   // 0..63
#pragma unroll
            for (int half = 0; half < 2; half++) {
                int rloc = warpM * 32 + mt * 16 + g + half * 8;
                long gn = blockRow + rloc;
                if (gn < N) {
                    float x = acc[mt][nti][half * 2 + 0];
                    float t = acc[mt][nti][half * 2 + 1];
                    if (fabsf(t - 1.0f) < 1e-3f) {
                        float s = 0.0f;
                        const float* ar = &Asm[rloc * AS];
                        const float* wt = Wlt2 + j * 128;
                        const float* wr = Wrt2 + j * 128;
#pragma unroll 4
                        for (int k = 0; k < 128; k++) s += ar[k] * wt[k];
#pragma unroll 4
                        for (int k = 0; k < 128; k++) s += ar[128 + k] * wr[k];
                        t = s;
                    }
                    float sg = sigmoidf_(x);
                    out[gn * 64 + j] = (t >= 1.0f) ? sg : 0.0f;
                }
            }
        }
    }
}

extern "C" void kernel_launch(void* const* d_in, const int* in_sizes, int n_in,
                              void* d_out, int out_size)
{
    const float* h0   = (const float*)d_in[0];
    const float* h1   = (const float*)d_in[1];
    const float* h2   = (const float*)d_in[2];
    const float* Wl1  = (const float*)d_in[3];
    const float* Wr1  = (const float*)d_in[4];
    const float* Wlt1 = (const float*)d_in[5];
    const float* Wrt1 = (const float*)d_in[6];
    const float* Wl2  = (const float*)d_in[7];
    const float* Wr2  = (const float*)d_in[8];
    const float* Wlt2 = (const float*)d_in[9];
    const float* Wrt2 = (const float*)d_in[10];

    int N = in_sizes[0] / 128;

    int smem1 = (128 * AS + 2 * 256 * BS) * 4;   // 206,848 B
    int smem2 = (128 * AS + 2 * 128 * BS) * 4;   // 169,984 B
    cudaFuncSetAttribute(signn_l1, cudaFuncAttributeMaxDynamicSharedMemorySize, smem1);
    cudaFuncSetAttribute(signn_l2, cudaFuncAttributeMaxDynamicSharedMemorySize, smem2);

    long rows = 6L * N;
    int grid1 = (int)((rows + 127) / 128);
    int grid2 = (N + 127) / 128;

    signn_l1<<<grid1, 512, smem1>>>(h0, h1, h2, Wl1, Wr1, Wlt1, Wrt1, N);
    signn_l2<<<grid2, 256, smem2>>>(Wl2, Wr2, Wlt2, Wrt2, (float*)d_out, N);
}

// round 3
// speedup vs baseline: 3.1723x; 1.7732x over previous
#include <cuda_runtime.h>
#include <cuda_bf16.h>
#include <math.h>
#include <stdint.h>

// ---------------- global scratch ----------------
__device__ float    g_outs[76800000];          // layer-1 out_s: 600000 x 128
__device__ uint32_t g_B1h[256 * 128], g_B1l[256 * 128];   // layer-1 B, packed bf16x2
__device__ uint32_t g_B2h[128 * 128], g_B2l[128 * 128];   // layer-2 B

// ---------------- helpers ----------------
static __device__ __forceinline__ void split2(float x, float y, uint32_t& ph, uint32_t& pl) {
    __nv_bfloat16 hx = __float2bfloat16(x);
    __nv_bfloat16 hy = __float2bfloat16(y);
    float rx = x - __bfloat162float(hx);
    float ry = y - __bfloat162float(hy);
    __nv_bfloat162 H; H.x = hx; H.y = hy;
    __nv_bfloat162 L; L.x = __float2bfloat16(rx); L.y = __float2bfloat16(ry);
    ph = *reinterpret_cast<uint32_t*>(&H);
    pl = *reinterpret_cast<uint32_t*>(&L);
}

static __device__ __forceinline__ void mma16(float c[4], const uint32_t a[4],
                                             uint32_t b0, uint32_t b1) {
    asm volatile(
        "mma.sync.aligned.m16n8k16.row.col.f32.bf16.bf16.f32 "
        "{%0,%1,%2,%3}, {%4,%5,%6,%7}, {%8,%9}, {%0,%1,%2,%3};"
        : "+f"(c[0]), "+f"(c[1]), "+f"(c[2]), "+f"(c[3])
        : "r"(a[0]), "r"(a[1]), "r"(a[2]), "r"(a[3]), "r"(b0), "r"(b1));
}

static __device__ __forceinline__ void cpa16(uint32_t* dst, const uint32_t* src) {
    uint32_t s = (uint32_t)__cvta_generic_to_shared(dst);
    asm volatile("cp.async.cg.shared.global [%0], [%1], 16;\n" :: "r"(s), "l"(src));
}
static __device__ __forceinline__ void cpa_commit() {
    asm volatile("cp.async.commit_group;\n" ::: "memory");
}

static __device__ __forceinline__ float sigmoidf_(float v) {
    return 1.0f / (1.0f + expf(-v));
}

// exact-ish recompute of t for spike decisions near the threshold
static __device__ __noinline__ float recompute_t(const uint32_t* AHrow, const uint32_t* ALrow,
                                                 const float* __restrict__ wt,
                                                 const float* __restrict__ wr) {
    float s = 0.0f;
    for (int k2 = 0; k2 < 64; k2++) {
        __nv_bfloat162 uh = *reinterpret_cast<const __nv_bfloat162*>(&AHrow[k2]);
        __nv_bfloat162 ul = *reinterpret_cast<const __nv_bfloat162*>(&ALrow[k2]);
        float a0 = __bfloat162float(uh.x) + __bfloat162float(ul.x);
        float a1 = __bfloat162float(uh.y) + __bfloat162float(ul.y);
        s += a0 * wt[2 * k2] + a1 * wt[2 * k2 + 1];
    }
    for (int k2 = 64; k2 < 128; k2++) {
        __nv_bfloat162 uh = *reinterpret_cast<const __nv_bfloat162*>(&AHrow[k2]);
        __nv_bfloat162 ul = *reinterpret_cast<const __nv_bfloat162*>(&ALrow[k2]);
        float a0 = __bfloat162float(uh.x) + __bfloat162float(ul.x);
        float a1 = __bfloat162float(uh.y) + __bfloat162float(ul.y);
        s += a0 * wr[2 * k2 - 128] + a1 * wr[2 * k2 - 127];
    }
    return s;
}

// ---------------- weight pre-split ----------------
// col c (interleaved): j = c>>1, tt = c&1 (0 -> x-gate Wl/Wr, 1 -> t-gate Wlt/Wrt)
// k < 128 -> self weights, k >= 128 -> neigh weights. Layout [col][k/2] packed bf16x2.
__global__ void presplit(const float* __restrict__ Wl1, const float* __restrict__ Wr1,
                         const float* __restrict__ Wlt1, const float* __restrict__ Wrt1,
                         const float* __restrict__ Wl2, const float* __restrict__ Wr2,
                         const float* __restrict__ Wlt2, const float* __restrict__ Wrt2) {
    int c = blockIdx.x;          // 0..383
    int t = threadIdx.x;         // 0..127 -> k pair (2t, 2t+1)
    bool is1 = c < 256;
    int cc = is1 ? c : c - 256;
    int j = cc >> 1, tt = cc & 1;
    int k = 2 * t;
    const float* base;
    if (is1) base = (k < 128) ? (tt ? Wlt1 : Wl1) : (tt ? Wrt1 : Wr1);
    else     base = (k < 128) ? (tt ? Wlt2 : Wl2) : (tt ? Wrt2 : Wr2);
    int kk = k & 127;
    float x = base[j * 128 + kk], y = base[j * 128 + kk + 1];
    uint32_t ph, pl;
    split2(x, y, ph, pl);
    if (is1) { g_B1h[cc * 128 + t] = ph; g_B1l[cc * 128 + t] = pl; }
    else     { g_B2h[cc * 128 + t] = ph; g_B2l[cc * 128 + t] = pl; }
}

// ---------------- fused GEMM + epilogue ----------------
// L1: rows = 6N virtual rows (h0 nodes then h1 nodes); writes g_outs[row][128]
// L2: rows = N nodes (A from g_outs); writes out[row][64]
#define AP 132   // uint32 per A row (128 data + 4 pad)
#define BP 20    // uint32 per B col per 32-k chunk (16 data + 4 pad)

template <bool L1>
__global__ void __launch_bounds__(512, 1)
signn_gemm(const float* __restrict__ h0, const float* __restrict__ h1,
           const float* __restrict__ h2,
           const float* __restrict__ Wt_self, const float* __restrict__ Wt_neigh,
           float* __restrict__ outp, int N)
{
    constexpr int NCOL = L1 ? 256 : 128;
    constexpr int NTI  = NCOL / 32;      // n-tiles per warp
    constexpr int OC   = L1 ? 128 : 64;  // output cols

    extern __shared__ uint32_t sm[];
    uint32_t* AH = sm;
    uint32_t* AL = sm + 128 * AP;
    uint32_t* Bb = sm + 2 * 128 * AP;    // 4 segments: [buf][h/l], each NCOL*BP

    const int tid = threadIdx.x;
    const int w = tid >> 5, l = tid & 31;
    const int g = l >> 2, tg = l & 3;
    const int warpM = w >> 2, warpN = w & 3;
    const long rows = L1 ? 6L * N : (long)N;
    const long blockRow = (long)blockIdx.x * 128;
    const uint32_t* Bh = L1 ? g_B1h : g_B2h;
    const uint32_t* Bl = L1 ? g_B1l : g_B2l;
    float* op = L1 ? g_outs : outp;

    // ---- prefetch B chunk 0 via cp.async (overlaps A staging) ----
    {
#pragma unroll
        for (int arr = 0; arr < 2; arr++) {
            const uint32_t* src = arr ? Bl : Bh;
            uint32_t* dst = Bb + arr * NCOL * BP;
#pragma unroll
            for (int it = 0; it < NCOL * 4 / 512; it++) {
                int o = it * 512 + tid;
                int col = o >> 2, q = o & 3;
                cpa16(dst + col * BP + 4 * q, src + col * 128 + 4 * q);
            }
        }
        cpa_commit();
    }

    // ---- stage A: gather rows, split to bf16 hi/lo, pack pairs ----
#pragma unroll
    for (int rr = 0; rr < 8; rr++) {
        int row = w * 8 + rr;
        long gr = blockRow + row;
        long grc = gr < rows ? gr : rows - 1;
        float4 xv, nv;
        if (L1) {
            if (grc < N) {
                xv = ((const float4*)h0)[grc * 32 + l];
                const float4* p = (const float4*)h1 + grc * 5 * 32 + l;
                float4 a0 = p[0], a1 = p[32], a2 = p[64], a3 = p[96], a4 = p[128];
                nv.x = (a0.x + a1.x + a2.x + a3.x + a4.x) * 0.2f;
                nv.y = (a0.y + a1.y + a2.y + a3.y + a4.y) * 0.2f;
                nv.z = (a0.z + a1.z + a2.z + a3.z + a4.z) * 0.2f;
                nv.w = (a0.w + a1.w + a2.w + a3.w + a4.w) * 0.2f;
            } else {
                long q = grc - N;
                xv = ((const float4*)h1)[q * 32 + l];
                const float4* p = (const float4*)h2 + q * 2 * 32 + l;
                float4 a0 = p[0], a1 = p[32];
                nv.x = (a0.x + a1.x) * 0.5f;
                nv.y = (a0.y + a1.y) * 0.5f;
                nv.z = (a0.z + a1.z) * 0.5f;
                nv.w = (a0.w + a1.w) * 0.5f;
            }
        } else {
            xv = ((const float4*)g_outs)[grc * 32 + l];
            const float4* p = (const float4*)g_outs + ((long)N + grc * 5) * 32 + l;
            float4 a0 = p[0], a1 = p[32], a2 = p[64], a3 = p[96], a4 = p[128];
            nv.x = (a0.x + a1.x + a2.x + a3.x + a4.x) * 0.2f;
            nv.y = (a0.y + a1.y + a2.y + a3.y + a4.y) * 0.2f;
            nv.z = (a0.z + a1.z + a2.z + a3.z + a4.z) * 0.2f;
            nv.w = (a0.w + a1.w + a2.w + a3.w + a4.w) * 0.2f;
        }
        uint32_t h0p, l0p, h1p, l1p;
        split2(xv.x, xv.y, h0p, l0p);
        split2(xv.z, xv.w, h1p, l1p);
        *(uint2*)&AH[row * AP + 2 * l] = make_uint2(h0p, h1p);
        *(uint2*)&AL[row * AP + 2 * l] = make_uint2(l0p, l1p);
        split2(nv.x, nv.y, h0p, l0p);
        split2(nv.z, nv.w, h1p, l1p);
        *(uint2*)&AH[row * AP + 64 + 2 * l] = make_uint2(h0p, h1p);
        *(uint2*)&AL[row * AP + 64 + 2 * l] = make_uint2(l0p, l1p);
    }

    float acc[2][NTI][4];
#pragma unroll
    for (int mt = 0; mt < 2; mt++)
#pragma unroll
        for (int nt = 0; nt < NTI; nt++)
#pragma unroll
            for (int e = 0; e < 4; e++) acc[mt][nt][e] = 0.0f;

    // ---- main loop: 8 chunks of BK=32, double-buffered B ----
#pragma unroll
    for (int kc = 0; kc < 8; kc++) {
        if (kc < 7) {   // prefetch next chunk into other buffer
            uint32_t* base = Bb + ((kc + 1) & 1) * 2 * NCOL * BP;
#pragma unroll
            for (int arr = 0; arr < 2; arr++) {
                const uint32_t* src = (arr ? Bl : Bh) + (kc + 1) * 16;
                uint32_t* dst = base + arr * NCOL * BP;
#pragma unroll
                for (int it = 0; it < NCOL * 4 / 512; it++) {
                    int o = it * 512 + tid;
                    int col = o >> 2, q = o & 3;
                    cpa16(dst + col * BP + 4 * q, src + col * 128 + 4 * q);
                }
            }
            cpa_commit();
            asm volatile("cp.async.wait_group 1;\n" ::: "memory");
        } else {
            asm volatile("cp.async.wait_group 0;\n" ::: "memory");
        }
        __syncthreads();

        const uint32_t* BHc = Bb + (kc & 1) * 2 * NCOL * BP;
        const uint32_t* BLc = BHc + NCOL * BP;
#pragma unroll
        for (int ks = 0; ks < 2; ks++) {
            int ab = kc * 16 + ks * 8;
            uint32_t ah[2][4], al[2][4];
#pragma unroll
            for (int mt = 0; mt < 2; mt++) {
                int r0 = (warpM * 32 + mt * 16 + g) * AP;
                ah[mt][0] = AH[r0 + ab + tg];
                ah[mt][1] = AH[r0 + 8 * AP + ab + tg];
                ah[mt][2] = AH[r0 + ab + tg + 4];
                ah[mt][3] = AH[r0 + 8 * AP + ab + tg + 4];
                al[mt][0] = AL[r0 + ab + tg];
                al[mt][1] = AL[r0 + 8 * AP + ab + tg];
                al[mt][2] = AL[r0 + ab + tg + 4];
                al[mt][3] = AL[r0 + 8 * AP + ab + tg + 4];
            }
#pragma unroll
            for (int nt = 0; nt < NTI; nt++) {
                int cb = (warpN * NTI * 8 + nt * 8 + g) * BP + ks * 8 + tg;
                uint32_t bh0 = BHc[cb], bh1 = BHc[cb + 4];
                uint32_t bl0 = BLc[cb], bl1 = BLc[cb + 4];
#pragma unroll
                for (int mt = 0; mt < 2; mt++) {
                    mma16(acc[mt][nt], ah[mt], bh0, bh1);
                    mma16(acc[mt][nt], ah[mt], bl0, bl1);
                    mma16(acc[mt][nt], al[mt], bh0, bh1);
                }
            }
        }
        if (kc < 7) __syncthreads();
    }

    // ---- epilogue: out = sigmoid(x) * spike(t), guarded near threshold ----
#pragma unroll
    for (int mt = 0; mt < 2; mt++) {
#pragma unroll
        for (int nt = 0; nt < NTI; nt++) {
            int j = warpN * (NTI * 4) + nt * 4 + tg;
#pragma unroll
            for (int half = 0; half < 2; half++) {
                int rloc = warpM * 32 + mt * 16 + g + half * 8;
                long gr = blockRow + rloc;
                if (gr < rows) {
                    float x = acc[mt][nt][half * 2 + 0];
                    float t = acc[mt][nt][half * 2 + 1];
                    if (fabsf(t - 1.0f) < 5e-4f)
                        t = recompute_t(&AH[rloc * AP], &AL[rloc * AP],
                                        Wt_self + j * 128, Wt_neigh + j * 128);
                    op[gr * OC + j] = (t >= 1.0f) ? sigmoidf_(x) : 0.0f;
                }
            }
        }
    }
}

extern "C" void kernel_launch(void* const* d_in, const int* in_sizes, int n_in,
                              void* d_out, int out_size)
{
    const float* h0   = (const float*)d_in[0];
    const float* h1   = (const float*)d_in[1];
    const float* h2   = (const float*)d_in[2];
    const float* Wl1  = (const float*)d_in[3];
    const float* Wr1  = (const float*)d_in[4];
    const float* Wlt1 = (const float*)d_in[5];
    const float* Wrt1 = (const float*)d_in[6];
    const float* Wl2  = (const float*)d_in[7];
    const float* Wr2  = (const float*)d_in[8];
    const float* Wlt2 = (const float*)d_in[9];
    const float* Wrt2 = (const float*)d_in[10];

    int N = in_sizes[0] / 128;

    int smem1 = (2 * 128 * AP + 4 * 256 * BP) * 4;   // 217,088 B
    int smem2 = (2 * 128 * AP + 4 * 128 * BP) * 4;   // 176,128 B
    cudaFuncSetAttribute(signn_gemm<true>,  cudaFuncAttributeMaxDynamicSharedMemorySize, smem1);
    cudaFuncSetAttribute(signn_gemm<false>, cudaFuncAttributeMaxDynamicSharedMemorySize, smem2);

    long rows = 6L * N;
    int grid1 = (int)((rows + 127) / 128);
    int grid2 = (N + 127) / 128;

    presplit<<<384, 128>>>(Wl1, Wr1, Wlt1, Wrt1, Wl2, Wr2, Wlt2, Wrt2);
    signn_gemm<true><<<grid1, 512, smem1>>>(h0, h1, h2, Wlt1, Wrt1, nullptr, N);
    signn_gemm<false><<<grid2, 512, smem2>>>(nullptr, nullptr, nullptr, Wlt2, Wrt2,
                                             (float*)d_out, N);
}